// round 1
// baseline (speedup 1.0000x reference)
#include <cuda_runtime.h>
#include <cstddef>

#define NN 50000
#define NE 800000
#define D  128
#define NL 5
#define BN_EPS 1e-3f

// Scratch for pooled aggregation result (25.6 MB) — static device array (no allocs allowed).
__device__ float g_pooled[NN * D];

// ---------------------------------------------------------------------------
// pooled = (1 + eps[l]) * h       (vectorized float4)
// ---------------------------------------------------------------------------
__global__ void init_pooled_k(const float* __restrict__ h,
                              const float* __restrict__ eps, int l) {
    int i = blockIdx.x * 256 + threadIdx.x;
    if (i >= NN * D / 4) return;
    float e = 1.0f + __ldg(&eps[l]);
    float4 v = ((const float4*)h)[i];
    v.x *= e; v.y *= e; v.z *= e; v.w *= e;
    ((float4*)g_pooled)[i] = v;
}

// ---------------------------------------------------------------------------
// pooled[dst] += h[src]  — one warp per edge, float4 lanes, vector red.global
// ---------------------------------------------------------------------------
__global__ void scatter_k(const float* __restrict__ h,
                          const int* __restrict__ src,
                          const int* __restrict__ dst) {
    int gt   = blockIdx.x * 256 + threadIdx.x;
    int e    = gt >> 5;
    int lane = gt & 31;
    if (e >= NE) return;
    int s = __ldg(&src[e]);
    int d = __ldg(&dst[e]);
    float4 v = __ldg(((const float4*)h) + s * 32 + lane);
    float* p = g_pooled + (size_t)d * D + lane * 4;
    asm volatile("red.global.add.v4.f32 [%0], {%1,%2,%3,%4};"
                 :: "l"(p), "f"(v.x), "f"(v.y), "f"(v.z), "f"(v.w)
                 : "memory");
}

// ---------------------------------------------------------------------------
// Fused MLP: out = relu(BN(relu(pooled@W1 + b1) @ W2 + b2))
// Block tile 128(M) x 128(N), 256 threads, 8x8 per-thread micro-tile.
// W1, W2, A/Z tile staged in shared memory (198 KB dynamic smem, 1 CTA/SM).
// ---------------------------------------------------------------------------
__global__ void __launch_bounds__(256, 1) mlp_k(
    float* __restrict__ out,
    const float* __restrict__ W1, const float* __restrict__ b1,
    const float* __restrict__ W2, const float* __restrict__ b2,
    const float* __restrict__ gamma, const float* __restrict__ beta,
    const float* __restrict__ bmean, const float* __restrict__ bvar)
{
    extern __shared__ float sm[];
    float* sW1 = sm;            // 16384 floats
    float* sW2 = sm + 16384;    // 16384 floats
    float* sA  = sm + 32768;    // 16384 floats (A tile, then Z tile)
    float* sB1 = sm + 49152;    // 128
    float* sS  = sm + 49280;    // 128 (BN scale)
    float* sT  = sm + 49408;    // 128 (BN shift incl. b2)

    const int tid = threadIdx.x;

    if (tid < 128) {
        float s = __ldg(&gamma[tid]) * rsqrtf(__ldg(&bvar[tid]) + BN_EPS);
        sS[tid]  = s;
        sT[tid]  = __ldg(&b2[tid]) * s + __ldg(&beta[tid]) - __ldg(&bmean[tid]) * s;
        sB1[tid] = __ldg(&b1[tid]);
    }

    // Stage W1, W2 (128x128 each, row-major: W[k][c])
    #pragma unroll
    for (int i = 0; i < 16; i++) {
        int idx = tid + i * 256;                 // 0..4095 float4
        ((float4*)sW1)[idx] = ((const float4*)W1)[idx];
        ((float4*)sW2)[idx] = ((const float4*)W2)[idx];
    }

    // Stage A tile (128 rows of pooled), zero-pad past N
    const int rowBase = blockIdx.x * 128;
    #pragma unroll
    for (int i = 0; i < 16; i++) {
        int idx = tid + i * 256;
        int r = idx >> 5, c = idx & 31;
        int gr = rowBase + r;
        float4 v = make_float4(0.f, 0.f, 0.f, 0.f);
        if (gr < NN) v = ((const float4*)g_pooled)[gr * 32 + c];
        ((float4*)sA)[idx] = v;
    }
    __syncthreads();

    const int r0 = (tid >> 4) * 8;   // 16 row-groups
    const int c0 = (tid & 15) * 8;   // 16 col-groups

    float acc[8][8];
    #pragma unroll
    for (int i = 0; i < 8; i++)
        #pragma unroll
        for (int j = 0; j < 8; j++) acc[i][j] = 0.f;

    // ---- GEMM1: acc = A @ W1 ----
    #pragma unroll 4
    for (int k = 0; k < D; k++) {
        float a[8], w[8];
        #pragma unroll
        for (int i = 0; i < 8; i++) a[i] = sA[(r0 + i) * D + k];
        float4 w0 = *(const float4*)&sW1[k * D + c0];
        float4 w1 = *(const float4*)&sW1[k * D + c0 + 4];
        w[0]=w0.x; w[1]=w0.y; w[2]=w0.z; w[3]=w0.w;
        w[4]=w1.x; w[5]=w1.y; w[6]=w1.z; w[7]=w1.w;
        #pragma unroll
        for (int i = 0; i < 8; i++)
            #pragma unroll
            for (int j = 0; j < 8; j++)
                acc[i][j] = fmaf(a[i], w[j], acc[i][j]);
    }
    __syncthreads();   // all warps done reading sA

    // ---- Z = relu(acc + b1) -> sA (overwrite) ----
    #pragma unroll
    for (int i = 0; i < 8; i++) {
        float4 z0, z1;
        z0.x = fmaxf(acc[i][0] + sB1[c0+0], 0.f);
        z0.y = fmaxf(acc[i][1] + sB1[c0+1], 0.f);
        z0.z = fmaxf(acc[i][2] + sB1[c0+2], 0.f);
        z0.w = fmaxf(acc[i][3] + sB1[c0+3], 0.f);
        z1.x = fmaxf(acc[i][4] + sB1[c0+4], 0.f);
        z1.y = fmaxf(acc[i][5] + sB1[c0+5], 0.f);
        z1.z = fmaxf(acc[i][6] + sB1[c0+6], 0.f);
        z1.w = fmaxf(acc[i][7] + sB1[c0+7], 0.f);
        *(float4*)&sA[(r0+i)*D + c0]     = z0;
        *(float4*)&sA[(r0+i)*D + c0 + 4] = z1;
    }
    __syncthreads();

    #pragma unroll
    for (int i = 0; i < 8; i++)
        #pragma unroll
        for (int j = 0; j < 8; j++) acc[i][j] = 0.f;

    // ---- GEMM2: acc = Z @ W2 ----
    #pragma unroll 4
    for (int k = 0; k < D; k++) {
        float a[8], w[8];
        #pragma unroll
        for (int i = 0; i < 8; i++) a[i] = sA[(r0 + i) * D + k];
        float4 w0 = *(const float4*)&sW2[k * D + c0];
        float4 w1 = *(const float4*)&sW2[k * D + c0 + 4];
        w[0]=w0.x; w[1]=w0.y; w[2]=w0.z; w[3]=w0.w;
        w[4]=w1.x; w[5]=w1.y; w[6]=w1.z; w[7]=w1.w;
        #pragma unroll
        for (int i = 0; i < 8; i++)
            #pragma unroll
            for (int j = 0; j < 8; j++)
                acc[i][j] = fmaf(a[i], w[j], acc[i][j]);
    }

    // ---- Epilogue: out = relu(acc * S + T) ----
    #pragma unroll
    for (int i = 0; i < 8; i++) {
        int gr = rowBase + r0 + i;
        if (gr < NN) {
            float4 o0, o1;
            o0.x = fmaxf(fmaf(acc[i][0], sS[c0+0], sT[c0+0]), 0.f);
            o0.y = fmaxf(fmaf(acc[i][1], sS[c0+1], sT[c0+1]), 0.f);
            o0.z = fmaxf(fmaf(acc[i][2], sS[c0+2], sT[c0+2]), 0.f);
            o0.w = fmaxf(fmaf(acc[i][3], sS[c0+3], sT[c0+3]), 0.f);
            o1.x = fmaxf(fmaf(acc[i][4], sS[c0+4], sT[c0+4]), 0.f);
            o1.y = fmaxf(fmaf(acc[i][5], sS[c0+5], sT[c0+5]), 0.f);
            o1.z = fmaxf(fmaf(acc[i][6], sS[c0+6], sT[c0+6]), 0.f);
            o1.w = fmaxf(fmaf(acc[i][7], sS[c0+7], sT[c0+7]), 0.f);
            ((float4*)out)[gr*32 + (c0>>2)]     = o0;
            ((float4*)out)[gr*32 + (c0>>2) + 1] = o1;
        }
    }
}

// ---------------------------------------------------------------------------
extern "C" void kernel_launch(void* const* d_in, const int* in_sizes, int n_in,
                              void* d_out, int out_size) {
    const float* x     = (const float*)d_in[0];
    const int*   esrc  = (const int*)  d_in[1];
    const int*   edst  = (const int*)  d_in[2];
    const float* eps   = (const float*)d_in[3];
    const float* W1    = (const float*)d_in[4];
    const float* b1    = (const float*)d_in[5];
    const float* W2    = (const float*)d_in[6];
    const float* b2    = (const float*)d_in[7];
    const float* gamma = (const float*)d_in[8];
    const float* beta  = (const float*)d_in[9];
    const float* bmean = (const float*)d_in[10];
    const float* bvar  = (const float*)d_in[11];
    float* out = (float*)d_out;

    const int SMEM_BYTES = (16384 * 3 + 128 * 3) * sizeof(float);  // 198144
    cudaFuncSetAttribute(mlp_k, cudaFuncAttributeMaxDynamicSharedMemorySize, SMEM_BYTES);

    // hidden_rep[0] = x
    cudaMemcpyAsync(out, x, (size_t)NN * D * sizeof(float), cudaMemcpyDeviceToDevice);

    const int initGrid    = (NN * D / 4 + 255) / 256;     // 6250
    const int scatterGrid = (NE * 32 + 255) / 256;        // 100000
    const int mlpGrid     = (NN + 127) / 128;             // 391

    for (int l = 0; l < NL; l++) {
        const float* h  = out + (size_t)l * NN * D;
        float*       hn = out + (size_t)(l + 1) * NN * D;
        init_pooled_k<<<initGrid, 256>>>(h, eps, l);
        scatter_k<<<scatterGrid, 256>>>(h, esrc, edst);
        mlp_k<<<mlpGrid, 256, SMEM_BYTES>>>(hn,
            W1 + (size_t)l * D * D, b1 + (size_t)l * D,
            W2 + (size_t)l * D * D, b2 + (size_t)l * D,
            gamma + (size_t)l * D, beta + (size_t)l * D,
            bmean + (size_t)l * D, bvar + (size_t)l * D);
    }
}

// round 3
// speedup vs baseline: 1.3470x; 1.3470x over previous
#include <cuda_runtime.h>
#include <cuda_bf16.h>
#include <cstdint>
#include <cstddef>

#define NN 50000
#define NE 800000
#define D  128
#define NL 5
#define BN_EPS 1e-3f
#define NTILES ((NN + 127) / 128)   // 391

// ---------------- scratch (no allocs allowed) ----------------
__device__ float g_pooled[NN * D];
// per layer: W1h, W1l, W2h, W2l — each 128x128 bf16, row-major [k][n]
__device__ __nv_bfloat16 g_wb[NL * 4 * 16384];

// ---------------- helpers ----------------
__device__ __forceinline__ uint32_t smem_u32(const void* p) {
    uint32_t a;
    asm("{ .reg .u64 t; cvta.to.shared.u64 t, %1; cvt.u32.u64 %0, t; }" : "=r"(a) : "l"(p));
    return a;
}
__device__ __forceinline__ void split_bf(float v, uint16_t& h, uint16_t& l) {
    __nv_bfloat16 hb = __float2bfloat16_rn(v);
    float rem = v - __bfloat162float(hb);
    h = __bfloat16_as_ushort(hb);
    l = __bfloat16_as_ushort(__float2bfloat16_rn(rem));
}
__device__ __forceinline__ void ldm_x4(uint32_t (&r)[4], uint32_t addr) {
    asm volatile("ldmatrix.sync.aligned.m8n8.x4.shared.b16 {%0,%1,%2,%3}, [%4];"
                 : "=r"(r[0]), "=r"(r[1]), "=r"(r[2]), "=r"(r[3]) : "r"(addr));
}
__device__ __forceinline__ void ldm_x4t(uint32_t (&r)[4], uint32_t addr) {
    asm volatile("ldmatrix.sync.aligned.m8n8.x4.trans.shared.b16 {%0,%1,%2,%3}, [%4];"
                 : "=r"(r[0]), "=r"(r[1]), "=r"(r[2]), "=r"(r[3]) : "r"(addr));
}
__device__ __forceinline__ void mma_bf16(float (&d)[4], const uint32_t (&a)[4],
                                         uint32_t b0, uint32_t b1) {
    asm volatile("mma.sync.aligned.m16n8k16.row.col.f32.bf16.bf16.f32 "
                 "{%0,%1,%2,%3}, {%4,%5,%6,%7}, {%8,%9}, {%0,%1,%2,%3};"
                 : "+f"(d[0]), "+f"(d[1]), "+f"(d[2]), "+f"(d[3])
                 : "r"(a[0]), "r"(a[1]), "r"(a[2]), "r"(a[3]), "r"(b0), "r"(b1));
}

// ---------------------------------------------------------------------------
// pooled = (1 + eps[l]) * h
// ---------------------------------------------------------------------------
__global__ void init_pooled_k(const float* __restrict__ h,
                              const float* __restrict__ eps, int l) {
    int i = blockIdx.x * 256 + threadIdx.x;
    if (i >= NN * D / 4) return;
    float e = 1.0f + __ldg(&eps[l]);
    float4 v = ((const float4*)h)[i];
    v.x *= e; v.y *= e; v.z *= e; v.w *= e;
    ((float4*)g_pooled)[i] = v;
}

// ---------------------------------------------------------------------------
// pooled[dst] += h[src]  — one warp per edge, float4 lanes, vector red.global
// ---------------------------------------------------------------------------
__global__ void scatter_k(const float* __restrict__ h,
                          const int* __restrict__ src,
                          const int* __restrict__ dst) {
    int gt   = blockIdx.x * 256 + threadIdx.x;
    int e    = gt >> 5;
    int lane = gt & 31;
    if (e >= NE) return;
    int s = __ldg(&src[e]);
    int d = __ldg(&dst[e]);
    float4 v = __ldg(((const float4*)h) + s * 32 + lane);
    float* p = g_pooled + (size_t)d * D + lane * 4;
    asm volatile("red.global.add.v4.f32 [%0], {%1,%2,%3,%4};"
                 :: "l"(p), "f"(v.x), "f"(v.y), "f"(v.z), "f"(v.w)
                 : "memory");
}

// ---------------------------------------------------------------------------
// Weight prep: fp32 W[k][n] -> bf16 hi/lo, plain row-major. grid = NL*2.
// ---------------------------------------------------------------------------
__global__ void prep_w_k(const float* __restrict__ W1, const float* __restrict__ W2) {
    int l   = blockIdx.x >> 1;
    int mat = blockIdx.x & 1;
    const float* W = (mat ? W2 : W1) + (size_t)l * 16384;
    __nv_bfloat16* dh = g_wb + ((size_t)(l * 2 + mat) * 2 + 0) * 16384;
    __nv_bfloat16* dl = g_wb + ((size_t)(l * 2 + mat) * 2 + 1) * 16384;
    for (int i = threadIdx.x; i < 16384; i += 256) {
        uint16_t hb, lb;
        split_bf(__ldg(&W[i]), hb, lb);
        dh[i] = __ushort_as_bfloat16(hb);
        dl[i] = __ushort_as_bfloat16(lb);
    }
}

// ---------------------------------------------------------------------------
// Tensor-core fused MLP via mma.sync bf16 (3-term split, fp32 accum).
// Persistent, 148 CTAs x 256 threads. Tile 128x128; warp grid 4(M) x 2(N),
// warp tile 32x64. Rows padded to 272B in SMEM (conflict-free ldmatrix).
// ---------------------------------------------------------------------------
#define LDB     272                 // bytes per 128-col bf16 row (136 el)
#define MATSZ   (128 * LDB)         // 34816
#define AH_OFF  0
#define AL_OFF  MATSZ
#define W1H_OFF (2 * MATSZ)
#define W1L_OFF (3 * MATSZ)
#define W2H_OFF (4 * MATSZ)
#define W2L_OFF (5 * MATSZ)
#define PB1_OFF (6 * MATSZ)         // 208896
#define PS_OFF  (PB1_OFF + 512)
#define PT_OFF  (PS_OFF + 512)
#define SMEM_REQ (PT_OFF + 512)     // 210432

__device__ __forceinline__ void gemm3(uint32_t sbase, uint32_t ahOff, uint32_t alOff,
                                      uint32_t whOff, uint32_t wlOff,
                                      int wm, int wn, int lane, float acc[2][8][4]) {
    const int lane15 = lane & 15;
    const int lhalf  = (lane >> 4) << 3;
    const uint32_t aRowBase = (uint32_t)(wm * 32 + lane15) * LDB + (uint32_t)lhalf * 2;
    const uint32_t bBaseOff = (uint32_t)lane15 * LDB + (uint32_t)(wn * 64 + lhalf) * 2;
    #pragma unroll 1
    for (int term = 0; term < 3; term++) {
        uint32_t aOff = (term == 2) ? alOff : ahOff;
        uint32_t wOff = (term == 1) ? wlOff : whOff;
        uint32_t aBase = sbase + aOff + aRowBase;
        uint32_t bBase = sbase + wOff + bBaseOff;
        #pragma unroll
        for (int ks = 0; ks < 8; ks++) {
            uint32_t a0[4], a1[4];
            ldm_x4(a0, aBase + ks * 32);
            ldm_x4(a1, aBase + 16 * LDB + ks * 32);
            uint32_t b[4][4];
            #pragma unroll
            for (int np = 0; np < 4; np++)
                ldm_x4t(b[np], bBase + (uint32_t)ks * (16 * LDB) + np * 32);
            #pragma unroll
            for (int nt = 0; nt < 8; nt++) {
                mma_bf16(acc[0][nt], a0, b[nt >> 1][(nt & 1) * 2], b[nt >> 1][(nt & 1) * 2 + 1]);
                mma_bf16(acc[1][nt], a1, b[nt >> 1][(nt & 1) * 2], b[nt >> 1][(nt & 1) * 2 + 1]);
            }
        }
    }
}

__global__ void __launch_bounds__(256, 1) mlp_mma_k(
    float* __restrict__ out, int layer,
    const float* __restrict__ b1, const float* __restrict__ b2,
    const float* __restrict__ gamma, const float* __restrict__ beta,
    const float* __restrict__ bmean, const float* __restrict__ bvar)
{
    extern __shared__ char sm[];
    const uint32_t sbase = smem_u32(sm);
    const int tid  = threadIdx.x;
    const int wid  = tid >> 5;
    const int lane = tid & 31;
    const int wm   = wid & 3;       // 4 M-groups of 32 rows
    const int wn   = wid >> 2;      // 2 N-groups of 64 cols

    float* B1f = (float*)(sm + PB1_OFF);
    float* Sf  = (float*)(sm + PS_OFF);
    float* Tf  = (float*)(sm + PT_OFF);
    if (tid < 128) {
        float s = __ldg(&gamma[tid]) * rsqrtf(__ldg(&bvar[tid]) + BN_EPS);
        Sf[tid]  = s;
        Tf[tid]  = __ldg(&b2[tid]) * s + __ldg(&beta[tid]) - __ldg(&bmean[tid]) * s;
        B1f[tid] = __ldg(&b1[tid]);
    }

    // Stage 4 split-weight matrices into padded SMEM (global is contiguous
    // per layer: W1h, W1l, W2h, W2l; 8192 uint4 total)
    {
        const uint4* wsrc = (const uint4*)(g_wb + (size_t)layer * 4 * 16384);
        #pragma unroll
        for (int it = 0; it < 32; it++) {
            int idx = tid + it * 256;        // 0..8191
            int mat = idx >> 11;             // 0..3
            int j   = idx & 2047;
            int k   = j >> 4, c = j & 15;
            *(uint4*)(sm + W1H_OFF + mat * MATSZ + k * LDB + c * 16) = __ldg(&wsrc[idx]);
        }
    }
    __syncthreads();

    const int rEp = lane >> 2;               // 0..7 epilogue row-in-8
    const int cEp = (lane & 3) * 2;          // 0,2,4,6 epilogue col pair

    for (int t = blockIdx.x; t < NTILES; t += gridDim.x) {
        const int rowBase = t * 128;

        // ---- load + split A tile (fp32 -> bf16 hi/lo) ----
        #pragma unroll
        for (int i = 0; i < 16; i++) {
            int idx = tid + i * 256;          // 0..4095 float4 units
            int ar = idx >> 5, c4 = idx & 31;
            int gr = rowBase + ar;
            float4 v = make_float4(0.f, 0.f, 0.f, 0.f);
            if (gr < NN) v = __ldg(((const float4*)g_pooled) + (size_t)gr * 32 + c4);
            uint16_t hx,lx,hy,ly,hz,lz,hw,lw;
            split_bf(v.x,hx,lx); split_bf(v.y,hy,ly); split_bf(v.z,hz,lz); split_bf(v.w,hw,lw);
            uint32_t off = (uint32_t)ar * LDB + (uint32_t)c4 * 8;
            uint2 hv = make_uint2((uint32_t)hx | ((uint32_t)hy << 16),
                                  (uint32_t)hz | ((uint32_t)hw << 16));
            uint2 lv = make_uint2((uint32_t)lx | ((uint32_t)ly << 16),
                                  (uint32_t)lz | ((uint32_t)lw << 16));
            *(uint2*)(sm + AH_OFF + off) = hv;
            *(uint2*)(sm + AL_OFF + off) = lv;
        }
        __syncthreads();

        float acc[2][8][4];
        #pragma unroll
        for (int a = 0; a < 2; a++)
            #pragma unroll
            for (int b = 0; b < 8; b++)
                #pragma unroll
                for (int c = 0; c < 4; c++) acc[a][b][c] = 0.f;

        // ---- GEMM1 ----
        gemm3(sbase, AH_OFF, AL_OFF, W1H_OFF, W1L_OFF, wm, wn, lane, acc);
        __syncthreads();   // everyone done reading A

        // ---- epilogue 1: Z = relu(D1 + b1) -> split back into AH/AL ----
        #pragma unroll
        for (int mt = 0; mt < 2; mt++) {
            #pragma unroll
            for (int nt = 0; nt < 8; nt++) {
                int row = wm * 32 + mt * 16 + rEp;
                int col = wn * 64 + nt * 8 + cEp;
                float f0 = fmaxf(acc[mt][nt][0] + B1f[col],     0.f);
                float f1 = fmaxf(acc[mt][nt][1] + B1f[col + 1], 0.f);
                float f2 = fmaxf(acc[mt][nt][2] + B1f[col],     0.f);
                float f3 = fmaxf(acc[mt][nt][3] + B1f[col + 1], 0.f);
                uint16_t h0,l0,h1,l1,h2,l2,h3,l3;
                split_bf(f0,h0,l0); split_bf(f1,h1,l1);
                split_bf(f2,h2,l2); split_bf(f3,h3,l3);
                uint32_t o0 = (uint32_t)row * LDB + (uint32_t)col * 2;
                uint32_t o1 = o0 + 8 * LDB;
                *(uint32_t*)(sm + AH_OFF + o0) = (uint32_t)h0 | ((uint32_t)h1 << 16);
                *(uint32_t*)(sm + AL_OFF + o0) = (uint32_t)l0 | ((uint32_t)l1 << 16);
                *(uint32_t*)(sm + AH_OFF + o1) = (uint32_t)h2 | ((uint32_t)h3 << 16);
                *(uint32_t*)(sm + AL_OFF + o1) = (uint32_t)l2 | ((uint32_t)l3 << 16);
            }
        }
        __syncthreads();

        #pragma unroll
        for (int a = 0; a < 2; a++)
            #pragma unroll
            for (int b = 0; b < 8; b++)
                #pragma unroll
                for (int c = 0; c < 4; c++) acc[a][b][c] = 0.f;

        // ---- GEMM2 ----
        gemm3(sbase, AH_OFF, AL_OFF, W2H_OFF, W2L_OFF, wm, wn, lane, acc);

        // ---- epilogue 2: out = relu(D2 * S + T) ----
        #pragma unroll
        for (int mt = 0; mt < 2; mt++) {
            #pragma unroll
            for (int nt = 0; nt < 8; nt++) {
                int row = wm * 32 + mt * 16 + rEp;
                int col = wn * 64 + nt * 8 + cEp;
                int gr0 = rowBase + row;
                int gr1 = gr0 + 8;
                float2 o0, o1;
                o0.x = fmaxf(fmaf(acc[mt][nt][0], Sf[col],     Tf[col]),     0.f);
                o0.y = fmaxf(fmaf(acc[mt][nt][1], Sf[col + 1], Tf[col + 1]), 0.f);
                o1.x = fmaxf(fmaf(acc[mt][nt][2], Sf[col],     Tf[col]),     0.f);
                o1.y = fmaxf(fmaf(acc[mt][nt][3], Sf[col + 1], Tf[col + 1]), 0.f);
                if (gr0 < NN) *(float2*)(out + (size_t)gr0 * D + col) = o0;
                if (gr1 < NN) *(float2*)(out + (size_t)gr1 * D + col) = o1;
            }
        }
        __syncthreads();   // A buffers reusable next tile
    }
}

// ---------------------------------------------------------------------------
extern "C" void kernel_launch(void* const* d_in, const int* in_sizes, int n_in,
                              void* d_out, int out_size) {
    const float* x     = (const float*)d_in[0];
    const int*   esrc  = (const int*)  d_in[1];
    const int*   edst  = (const int*)  d_in[2];
    const float* eps   = (const float*)d_in[3];
    const float* W1    = (const float*)d_in[4];
    const float* b1    = (const float*)d_in[5];
    const float* W2    = (const float*)d_in[6];
    const float* b2    = (const float*)d_in[7];
    const float* gamma = (const float*)d_in[8];
    const float* beta  = (const float*)d_in[9];
    const float* bmean = (const float*)d_in[10];
    const float* bvar  = (const float*)d_in[11];
    float* out = (float*)d_out;

    static int smem_set = 0;
    if (!smem_set) {
        cudaFuncSetAttribute(mlp_mma_k, cudaFuncAttributeMaxDynamicSharedMemorySize, SMEM_REQ);
        smem_set = 1;
    }

    // hidden_rep[0] = x
    cudaMemcpyAsync(out, x, (size_t)NN * D * sizeof(float), cudaMemcpyDeviceToDevice);

    // one-shot weight split
    prep_w_k<<<NL * 2, 256>>>(W1, W2);

    const int initGrid    = (NN * D / 4 + 255) / 256;
    const int scatterGrid = (NE * 32 + 255) / 256;

    for (int l = 0; l < NL; l++) {
        const float* h  = out + (size_t)l * NN * D;
        float*       hn = out + (size_t)(l + 1) * NN * D;
        init_pooled_k<<<initGrid, 256>>>(h, eps, l);
        scatter_k<<<scatterGrid, 256>>>(h, esrc, edst);
        mlp_mma_k<<<148, 256, SMEM_REQ>>>(hn, l,
            b1 + (size_t)l * D, b2 + (size_t)l * D,
            gamma + (size_t)l * D, beta + (size_t)l * D,
            bmean + (size_t)l * D, bvar + (size_t)l * D);
    }
}

// round 4
// speedup vs baseline: 2.0082x; 1.4909x over previous
#include <cuda_runtime.h>
#include <cuda_bf16.h>
#include <cstdint>
#include <cstddef>

#define NN 50000
#define NE 800000
#define D  128
#define NL 5
#define BN_EPS 1e-3f
#define NTILES ((NN + 127) / 128)   // 391

// ---------------- scratch (no allocs allowed) ----------------
__device__ float g_pooled[NN * D];
__device__ __nv_bfloat16 g_wb[NL * 4 * 16384];   // W1h W1l W2h W2l per layer
__device__ int g_off[NN + 1];                    // CSR offsets (by dst)
__device__ int g_cur[NN];                        // fill cursors
__device__ int g_csr[NE];                        // src ids grouped by dst

// ---------------- helpers ----------------
__device__ __forceinline__ uint32_t smem_u32(const void* p) {
    uint32_t a;
    asm("{ .reg .u64 t; cvta.to.shared.u64 t, %1; cvt.u32.u64 %0, t; }" : "=r"(a) : "l"(p));
    return a;
}
__device__ __forceinline__ void split_bf(float v, uint16_t& h, uint16_t& l) {
    __nv_bfloat16 hb = __float2bfloat16_rn(v);
    float rem = v - __bfloat162float(hb);
    h = __bfloat16_as_ushort(hb);
    l = __bfloat16_as_ushort(__float2bfloat16_rn(rem));
}
__device__ __forceinline__ void ldm_x4(uint32_t (&r)[4], uint32_t addr) {
    asm volatile("ldmatrix.sync.aligned.m8n8.x4.shared.b16 {%0,%1,%2,%3}, [%4];"
                 : "=r"(r[0]), "=r"(r[1]), "=r"(r[2]), "=r"(r[3]) : "r"(addr));
}
__device__ __forceinline__ void ldm_x4t(uint32_t (&r)[4], uint32_t addr) {
    asm volatile("ldmatrix.sync.aligned.m8n8.x4.trans.shared.b16 {%0,%1,%2,%3}, [%4];"
                 : "=r"(r[0]), "=r"(r[1]), "=r"(r[2]), "=r"(r[3]) : "r"(addr));
}
__device__ __forceinline__ void mma_bf16(float (&d)[4], const uint32_t (&a)[4],
                                         uint32_t b0, uint32_t b1) {
    asm volatile("mma.sync.aligned.m16n8k16.row.col.f32.bf16.bf16.f32 "
                 "{%0,%1,%2,%3}, {%4,%5,%6,%7}, {%8,%9}, {%0,%1,%2,%3};"
                 : "+f"(d[0]), "+f"(d[1]), "+f"(d[2]), "+f"(d[3])
                 : "r"(a[0]), "r"(a[1]), "r"(a[2]), "r"(a[3]), "r"(b0), "r"(b1));
}

// ---------------------------------------------------------------------------
// CSR build (runs once per launch; edge list is launch-invariant)
// ---------------------------------------------------------------------------
__global__ void zero_off_k() {
    int i = blockIdx.x * 256 + threadIdx.x;
    if (i <= NN) g_off[i] = 0;
}
__global__ void hist_k(const int* __restrict__ dst) {
    int e = blockIdx.x * 256 + threadIdx.x;
    if (e < NE) atomicAdd(&g_off[__ldg(&dst[e]) + 1], 1);
}
// single-block inclusive scan over g_off[1..NN]; also writes g_cur
__global__ void scan_k() {
    __shared__ int s[1024];
    __shared__ int carry;
    if (threadIdx.x == 0) carry = 0;
    __syncthreads();
    for (int base = 0; base < NN; base += 1024) {
        int i = base + threadIdx.x;
        int v = (i < NN) ? g_off[i + 1] : 0;
        s[threadIdx.x] = v;
        __syncthreads();
        #pragma unroll
        for (int d = 1; d < 1024; d <<= 1) {
            int t = (threadIdx.x >= d) ? s[threadIdx.x - d] : 0;
            __syncthreads();
            s[threadIdx.x] += t;
            __syncthreads();
        }
        int inc = s[threadIdx.x] + carry;
        if (i < NN) {
            g_off[i + 1] = inc;
            g_cur[i] = inc - v;   // exclusive start = cursor init
        }
        __syncthreads();
        if (threadIdx.x == 1023) carry = inc;
        __syncthreads();
    }
}
__global__ void fill_k(const int* __restrict__ src, const int* __restrict__ dst) {
    int e = blockIdx.x * 256 + threadIdx.x;
    if (e >= NE) return;
    int p = atomicAdd(&g_cur[__ldg(&dst[e])], 1);
    g_csr[p] = __ldg(&src[e]);
}

// ---------------------------------------------------------------------------
// Aggregation: pooled[d] = (1+eps)*h[d] + sum_{src in csr[off[d]..off[d+1])} h[src]
// One warp per node; lane = one float4 (32 x 16B = 512B row).
// ---------------------------------------------------------------------------
__global__ void agg_k(const float* __restrict__ h,
                      const float* __restrict__ eps, int l) {
    int gt   = blockIdx.x * 256 + threadIdx.x;
    int node = gt >> 5;
    int lane = gt & 31;
    if (node >= NN) return;
    float e = 1.0f + __ldg(&eps[l]);
    float4 acc = __ldg(((const float4*)h) + (size_t)node * 32 + lane);
    acc.x *= e; acc.y *= e; acc.z *= e; acc.w *= e;
    int beg = g_off[node], end = g_off[node + 1];
    int j = beg;
    for (; j + 4 <= end; j += 4) {
        int s0 = __ldg(&g_csr[j]);
        int s1 = __ldg(&g_csr[j + 1]);
        int s2 = __ldg(&g_csr[j + 2]);
        int s3 = __ldg(&g_csr[j + 3]);
        float4 v0 = __ldg(((const float4*)h) + (size_t)s0 * 32 + lane);
        float4 v1 = __ldg(((const float4*)h) + (size_t)s1 * 32 + lane);
        float4 v2 = __ldg(((const float4*)h) + (size_t)s2 * 32 + lane);
        float4 v3 = __ldg(((const float4*)h) + (size_t)s3 * 32 + lane);
        acc.x += v0.x + v1.x + v2.x + v3.x;
        acc.y += v0.y + v1.y + v2.y + v3.y;
        acc.z += v0.z + v1.z + v2.z + v3.z;
        acc.w += v0.w + v1.w + v2.w + v3.w;
    }
    for (; j < end; j++) {
        int s0 = __ldg(&g_csr[j]);
        float4 v0 = __ldg(((const float4*)h) + (size_t)s0 * 32 + lane);
        acc.x += v0.x; acc.y += v0.y; acc.z += v0.z; acc.w += v0.w;
    }
    ((float4*)g_pooled)[(size_t)node * 32 + lane] = acc;
}

// ---------------------------------------------------------------------------
// Weight prep: fp32 W[k][n] -> bf16 hi/lo, row-major. grid = NL*2.
// ---------------------------------------------------------------------------
__global__ void prep_w_k(const float* __restrict__ W1, const float* __restrict__ W2) {
    int l   = blockIdx.x >> 1;
    int mat = blockIdx.x & 1;
    const float* W = (mat ? W2 : W1) + (size_t)l * 16384;
    __nv_bfloat16* dh = g_wb + ((size_t)(l * 2 + mat) * 2 + 0) * 16384;
    __nv_bfloat16* dl = g_wb + ((size_t)(l * 2 + mat) * 2 + 1) * 16384;
    for (int i = threadIdx.x; i < 16384; i += 256) {
        uint16_t hb, lb;
        split_bf(__ldg(&W[i]), hb, lb);
        dh[i] = __ushort_as_bfloat16(hb);
        dl[i] = __ushort_as_bfloat16(lb);
    }
}

// ---------------------------------------------------------------------------
// Tensor-core fused MLP via mma.sync bf16 (3-term split, fp32 accum).
// ---------------------------------------------------------------------------
#define LDB     272
#define MATSZ   (128 * LDB)
#define AH_OFF  0
#define AL_OFF  MATSZ
#define W1H_OFF (2 * MATSZ)
#define W1L_OFF (3 * MATSZ)
#define W2H_OFF (4 * MATSZ)
#define W2L_OFF (5 * MATSZ)
#define PB1_OFF (6 * MATSZ)
#define PS_OFF  (PB1_OFF + 512)
#define PT_OFF  (PS_OFF + 512)
#define SMEM_REQ (PT_OFF + 512)

__device__ __forceinline__ void gemm3(uint32_t sbase, uint32_t ahOff, uint32_t alOff,
                                      uint32_t whOff, uint32_t wlOff,
                                      int wm, int wn, int lane, float acc[2][8][4]) {
    const int lane15 = lane & 15;
    const int lhalf  = (lane >> 4) << 3;
    const uint32_t aRowBase = (uint32_t)(wm * 32 + lane15) * LDB + (uint32_t)lhalf * 2;
    const uint32_t bBaseOff = (uint32_t)lane15 * LDB + (uint32_t)(wn * 64 + lhalf) * 2;
    #pragma unroll 1
    for (int term = 0; term < 3; term++) {
        uint32_t aOff = (term == 2) ? alOff : ahOff;
        uint32_t wOff = (term == 1) ? wlOff : whOff;
        uint32_t aBase = sbase + aOff + aRowBase;
        uint32_t bBase = sbase + wOff + bBaseOff;
        #pragma unroll
        for (int ks = 0; ks < 8; ks++) {
            uint32_t a0[4], a1[4];
            ldm_x4(a0, aBase + ks * 32);
            ldm_x4(a1, aBase + 16 * LDB + ks * 32);
            uint32_t b[4][4];
            #pragma unroll
            for (int np = 0; np < 4; np++)
                ldm_x4t(b[np], bBase + (uint32_t)ks * (16 * LDB) + np * 32);
            #pragma unroll
            for (int nt = 0; nt < 8; nt++) {
                mma_bf16(acc[0][nt], a0, b[nt >> 1][(nt & 1) * 2], b[nt >> 1][(nt & 1) * 2 + 1]);
                mma_bf16(acc[1][nt], a1, b[nt >> 1][(nt & 1) * 2], b[nt >> 1][(nt & 1) * 2 + 1]);
            }
        }
    }
}

__global__ void __launch_bounds__(256, 1) mlp_mma_k(
    float* __restrict__ out, int layer,
    const float* __restrict__ b1, const float* __restrict__ b2,
    const float* __restrict__ gamma, const float* __restrict__ beta,
    const float* __restrict__ bmean, const float* __restrict__ bvar)
{
    extern __shared__ char sm[];
    const uint32_t sbase = smem_u32(sm);
    const int tid  = threadIdx.x;
    const int wid  = tid >> 5;
    const int lane = tid & 31;
    const int wm   = wid & 3;
    const int wn   = wid >> 2;

    float* B1f = (float*)(sm + PB1_OFF);
    float* Sf  = (float*)(sm + PS_OFF);
    float* Tf  = (float*)(sm + PT_OFF);
    if (tid < 128) {
        float s = __ldg(&gamma[tid]) * rsqrtf(__ldg(&bvar[tid]) + BN_EPS);
        Sf[tid]  = s;
        Tf[tid]  = __ldg(&b2[tid]) * s + __ldg(&beta[tid]) - __ldg(&bmean[tid]) * s;
        B1f[tid] = __ldg(&b1[tid]);
    }

    {
        const uint4* wsrc = (const uint4*)(g_wb + (size_t)layer * 4 * 16384);
        #pragma unroll
        for (int it = 0; it < 32; it++) {
            int idx = tid + it * 256;
            int mat = idx >> 11;
            int j   = idx & 2047;
            int k   = j >> 4, c = j & 15;
            *(uint4*)(sm + W1H_OFF + mat * MATSZ + k * LDB + c * 16) = __ldg(&wsrc[idx]);
        }
    }
    __syncthreads();

    const int rEp = lane >> 2;
    const int cEp = (lane & 3) * 2;

    for (int t = blockIdx.x; t < NTILES; t += gridDim.x) {
        const int rowBase = t * 128;

        #pragma unroll
        for (int i = 0; i < 16; i++) {
            int idx = tid + i * 256;
            int ar = idx >> 5, c4 = idx & 31;
            int gr = rowBase + ar;
            float4 v = make_float4(0.f, 0.f, 0.f, 0.f);
            if (gr < NN) v = __ldg(((const float4*)g_pooled) + (size_t)gr * 32 + c4);
            uint16_t hx,lx,hy,ly,hz,lz,hw,lw;
            split_bf(v.x,hx,lx); split_bf(v.y,hy,ly); split_bf(v.z,hz,lz); split_bf(v.w,hw,lw);
            uint32_t off = (uint32_t)ar * LDB + (uint32_t)c4 * 8;
            uint2 hv = make_uint2((uint32_t)hx | ((uint32_t)hy << 16),
                                  (uint32_t)hz | ((uint32_t)hw << 16));
            uint2 lv = make_uint2((uint32_t)lx | ((uint32_t)ly << 16),
                                  (uint32_t)lz | ((uint32_t)lw << 16));
            *(uint2*)(sm + AH_OFF + off) = hv;
            *(uint2*)(sm + AL_OFF + off) = lv;
        }
        __syncthreads();

        float acc[2][8][4];
        #pragma unroll
        for (int a = 0; a < 2; a++)
            #pragma unroll
            for (int b = 0; b < 8; b++)
                #pragma unroll
                for (int c = 0; c < 4; c++) acc[a][b][c] = 0.f;

        gemm3(sbase, AH_OFF, AL_OFF, W1H_OFF, W1L_OFF, wm, wn, lane, acc);
        __syncthreads();

        #pragma unroll
        for (int mt = 0; mt < 2; mt++) {
            #pragma unroll
            for (int nt = 0; nt < 8; nt++) {
                int row = wm * 32 + mt * 16 + rEp;
                int col = wn * 64 + nt * 8 + cEp;
                float f0 = fmaxf(acc[mt][nt][0] + B1f[col],     0.f);
                float f1 = fmaxf(acc[mt][nt][1] + B1f[col + 1], 0.f);
                float f2 = fmaxf(acc[mt][nt][2] + B1f[col],     0.f);
                float f3 = fmaxf(acc[mt][nt][3] + B1f[col + 1], 0.f);
                uint16_t h0,l0,h1,l1,h2,l2,h3,l3;
                split_bf(f0,h0,l0); split_bf(f1,h1,l1);
                split_bf(f2,h2,l2); split_bf(f3,h3,l3);
                uint32_t o0 = (uint32_t)row * LDB + (uint32_t)col * 2;
                uint32_t o1 = o0 + 8 * LDB;
                *(uint32_t*)(sm + AH_OFF + o0) = (uint32_t)h0 | ((uint32_t)h1 << 16);
                *(uint32_t*)(sm + AL_OFF + o0) = (uint32_t)l0 | ((uint32_t)l1 << 16);
                *(uint32_t*)(sm + AH_OFF + o1) = (uint32_t)h2 | ((uint32_t)h3 << 16);
                *(uint32_t*)(sm + AL_OFF + o1) = (uint32_t)l2 | ((uint32_t)l3 << 16);
            }
        }
        __syncthreads();

        #pragma unroll
        for (int a = 0; a < 2; a++)
            #pragma unroll
            for (int b = 0; b < 8; b++)
                #pragma unroll
                for (int c = 0; c < 4; c++) acc[a][b][c] = 0.f;

        gemm3(sbase, AH_OFF, AL_OFF, W2H_OFF, W2L_OFF, wm, wn, lane, acc);

        #pragma unroll
        for (int mt = 0; mt < 2; mt++) {
            #pragma unroll
            for (int nt = 0; nt < 8; nt++) {
                int row = wm * 32 + mt * 16 + rEp;
                int col = wn * 64 + nt * 8 + cEp;
                int gr0 = rowBase + row;
                int gr1 = gr0 + 8;
                float2 o0, o1;
                o0.x = fmaxf(fmaf(acc[mt][nt][0], Sf[col],     Tf[col]),     0.f);
                o0.y = fmaxf(fmaf(acc[mt][nt][1], Sf[col + 1], Tf[col + 1]), 0.f);
                o1.x = fmaxf(fmaf(acc[mt][nt][2], Sf[col],     Tf[col]),     0.f);
                o1.y = fmaxf(fmaf(acc[mt][nt][3], Sf[col + 1], Tf[col + 1]), 0.f);
                if (gr0 < NN) *(float2*)(out + (size_t)gr0 * D + col) = o0;
                if (gr1 < NN) *(float2*)(out + (size_t)gr1 * D + col) = o1;
            }
        }
        __syncthreads();
    }
}

// ---------------------------------------------------------------------------
extern "C" void kernel_launch(void* const* d_in, const int* in_sizes, int n_in,
                              void* d_out, int out_size) {
    const float* x     = (const float*)d_in[0];
    const int*   esrc  = (const int*)  d_in[1];
    const int*   edst  = (const int*)  d_in[2];
    const float* eps   = (const float*)d_in[3];
    const float* W1    = (const float*)d_in[4];
    const float* b1    = (const float*)d_in[5];
    const float* W2    = (const float*)d_in[6];
    const float* b2    = (const float*)d_in[7];
    const float* gamma = (const float*)d_in[8];
    const float* beta  = (const float*)d_in[9];
    const float* bmean = (const float*)d_in[10];
    const float* bvar  = (const float*)d_in[11];
    float* out = (float*)d_out;

    static int smem_set = 0;
    if (!smem_set) {
        cudaFuncSetAttribute(mlp_mma_k, cudaFuncAttributeMaxDynamicSharedMemorySize, SMEM_REQ);
        smem_set = 1;
    }

    // hidden_rep[0] = x
    cudaMemcpyAsync(out, x, (size_t)NN * D * sizeof(float), cudaMemcpyDeviceToDevice);

    // one-shot: weight split + CSR build
    prep_w_k<<<NL * 2, 256>>>(W1, W2);
    zero_off_k<<<(NN + 256) / 256, 256>>>();
    hist_k<<<(NE + 255) / 256, 256>>>(edst);
    scan_k<<<1, 1024>>>();
    fill_k<<<(NE + 255) / 256, 256>>>(esrc, edst);

    const int aggGrid = (NN * 32 + 255) / 256;   // 6250

    for (int l = 0; l < NL; l++) {
        const float* h  = out + (size_t)l * NN * D;
        float*       hn = out + (size_t)(l + 1) * NN * D;
        agg_k<<<aggGrid, 256>>>(h, eps, l);
        mlp_mma_k<<<148, 256, SMEM_REQ>>>(hn, l,
            b1 + (size_t)l * D, b2 + (size_t)l * D,
            gamma + (size_t)l * D, beta + (size_t)l * D,
            bmean + (size_t)l * D, bvar + (size_t)l * D);
    }
}

// round 5
// speedup vs baseline: 2.0109x; 1.0013x over previous
#include <cuda_runtime.h>
#include <cuda_bf16.h>
#include <cstdint>
#include <cstddef>

#define NN 50000
#define NE 800000
#define D  128
#define NL 5
#define BN_EPS 1e-3f
#define NTILES ((NN + 127) / 128)   // 391

// ---------------- scratch (no allocs allowed) ----------------
__device__ float g_pooled[NN * D];
__device__ __nv_bfloat16 g_wb[NL * 4 * 16384];   // W1h W1l W2h W2l per layer
__device__ int g_off[NN + 1];                    // CSR offsets (by dst)
__device__ int g_cur[NN];                        // fill cursors
__device__ int g_csr[NE];                        // src ids grouped by dst

// ---------------- helpers ----------------
__device__ __forceinline__ uint32_t smem_u32(const void* p) {
    uint32_t a;
    asm("{ .reg .u64 t; cvta.to.shared.u64 t, %1; cvt.u32.u64 %0, t; }" : "=r"(a) : "l"(p));
    return a;
}
__device__ __forceinline__ void split_bf(float v, uint16_t& h, uint16_t& l) {
    __nv_bfloat16 hb = __float2bfloat16_rn(v);
    float rem = v - __bfloat162float(hb);
    h = __bfloat16_as_ushort(hb);
    l = __bfloat16_as_ushort(__float2bfloat16_rn(rem));
}
__device__ __forceinline__ void ldm_x4(uint32_t (&r)[4], uint32_t addr) {
    asm volatile("ldmatrix.sync.aligned.m8n8.x4.shared.b16 {%0,%1,%2,%3}, [%4];"
                 : "=r"(r[0]), "=r"(r[1]), "=r"(r[2]), "=r"(r[3]) : "r"(addr));
}
__device__ __forceinline__ void ldm_x4t(uint32_t (&r)[4], uint32_t addr) {
    asm volatile("ldmatrix.sync.aligned.m8n8.x4.trans.shared.b16 {%0,%1,%2,%3}, [%4];"
                 : "=r"(r[0]), "=r"(r[1]), "=r"(r[2]), "=r"(r[3]) : "r"(addr));
}
__device__ __forceinline__ void mma_bf16(float (&d)[4], const uint32_t (&a)[4],
                                         uint32_t b0, uint32_t b1) {
    asm volatile("mma.sync.aligned.m16n8k16.row.col.f32.bf16.bf16.f32 "
                 "{%0,%1,%2,%3}, {%4,%5,%6,%7}, {%8,%9}, {%0,%1,%2,%3};"
                 : "+f"(d[0]), "+f"(d[1]), "+f"(d[2]), "+f"(d[3])
                 : "r"(a[0]), "r"(a[1]), "r"(a[2]), "r"(a[3]), "r"(b0), "r"(b1));
}

// ---------------------------------------------------------------------------
// CSR build (runs once per launch; edge list is launch-invariant)
// ---------------------------------------------------------------------------
__global__ void zero_off_k() {
    int i = blockIdx.x * 256 + threadIdx.x;
    if (i <= NN) g_off[i] = 0;
}
__global__ void hist_k(const int* __restrict__ dst) {
    int e = blockIdx.x * 256 + threadIdx.x;
    if (e < NE) atomicAdd(&g_off[__ldg(&dst[e]) + 1], 1);
}
// single-block raking scan: 1024 threads x 49 elements, two passes over L2.
#define SCAN_PER 49   // ceil(50000 / 1024)
__global__ void scan_k() {
    __shared__ int wsum[32];
    const int tid  = threadIdx.x;
    const int lane = tid & 31;
    const int wid  = tid >> 5;
    const int beg  = tid * SCAN_PER;
    const int end  = (beg + SCAN_PER < NN) ? beg + SCAN_PER : NN;

    // pass 1: per-thread total
    int sum = 0;
    for (int i = beg; i < end; i++) sum += g_off[i + 1];

    // block inclusive scan of thread totals (shuffle)
    int v = sum;
    #pragma unroll
    for (int d = 1; d < 32; d <<= 1) {
        int t = __shfl_up_sync(0xFFFFFFFFu, v, d);
        if (lane >= d) v += t;
    }
    if (lane == 31) wsum[wid] = v;
    __syncthreads();
    if (wid == 0) {
        int w = wsum[lane];
        #pragma unroll
        for (int d = 1; d < 32; d <<= 1) {
            int t = __shfl_up_sync(0xFFFFFFFFu, w, d);
            if (lane >= d) w += t;
        }
        wsum[lane] = w;
    }
    __syncthreads();

    // exclusive prefix for this thread
    int run = (v - sum) + (wid > 0 ? wsum[wid - 1] : 0);

    // pass 2: write inclusive offsets + cursors
    for (int i = beg; i < end; i++) {
        int c = g_off[i + 1];
        g_cur[i] = run;          // exclusive start = fill cursor
        run += c;
        g_off[i + 1] = run;      // inclusive
    }
}
__global__ void fill_k(const int* __restrict__ src, const int* __restrict__ dst) {
    int e = blockIdx.x * 256 + threadIdx.x;
    if (e >= NE) return;
    int p = atomicAdd(&g_cur[__ldg(&dst[e])], 1);
    g_csr[p] = __ldg(&src[e]);
}

// ---------------------------------------------------------------------------
// Aggregation: pooled[d] = (1+eps)*h[d] + sum_{src in csr[off[d]..off[d+1])} h[src]
// One warp per node; lane = one float4 (32 x 16B = 512B row).
// ---------------------------------------------------------------------------
__global__ void agg_k(const float* __restrict__ h,
                      const float* __restrict__ eps, int l) {
    int gt   = blockIdx.x * 256 + threadIdx.x;
    int node = gt >> 5;
    int lane = gt & 31;
    if (node >= NN) return;
    float e = 1.0f + __ldg(&eps[l]);
    float4 acc = __ldg(((const float4*)h) + (size_t)node * 32 + lane);
    acc.x *= e; acc.y *= e; acc.z *= e; acc.w *= e;
    int beg = g_off[node], end = g_off[node + 1];
    int j = beg;
    for (; j + 4 <= end; j += 4) {
        int s0 = __ldg(&g_csr[j]);
        int s1 = __ldg(&g_csr[j + 1]);
        int s2 = __ldg(&g_csr[j + 2]);
        int s3 = __ldg(&g_csr[j + 3]);
        float4 v0 = __ldg(((const float4*)h) + (size_t)s0 * 32 + lane);
        float4 v1 = __ldg(((const float4*)h) + (size_t)s1 * 32 + lane);
        float4 v2 = __ldg(((const float4*)h) + (size_t)s2 * 32 + lane);
        float4 v3 = __ldg(((const float4*)h) + (size_t)s3 * 32 + lane);
        acc.x += v0.x + v1.x + v2.x + v3.x;
        acc.y += v0.y + v1.y + v2.y + v3.y;
        acc.z += v0.z + v1.z + v2.z + v3.z;
        acc.w += v0.w + v1.w + v2.w + v3.w;
    }
    for (; j < end; j++) {
        int s0 = __ldg(&g_csr[j]);
        float4 v0 = __ldg(((const float4*)h) + (size_t)s0 * 32 + lane);
        acc.x += v0.x; acc.y += v0.y; acc.z += v0.z; acc.w += v0.w;
    }
    ((float4*)g_pooled)[(size_t)node * 32 + lane] = acc;
}

// ---------------------------------------------------------------------------
// Weight prep: fp32 W[k][n] -> bf16 hi/lo, row-major. grid = NL*2.
// ---------------------------------------------------------------------------
__global__ void prep_w_k(const float* __restrict__ W1, const float* __restrict__ W2) {
    int l   = blockIdx.x >> 1;
    int mat = blockIdx.x & 1;
    const float* W = (mat ? W2 : W1) + (size_t)l * 16384;
    __nv_bfloat16* dh = g_wb + ((size_t)(l * 2 + mat) * 2 + 0) * 16384;
    __nv_bfloat16* dl = g_wb + ((size_t)(l * 2 + mat) * 2 + 1) * 16384;
    for (int i = threadIdx.x; i < 16384; i += 256) {
        uint16_t hb, lb;
        split_bf(__ldg(&W[i]), hb, lb);
        dh[i] = __ushort_as_bfloat16(hb);
        dl[i] = __ushort_as_bfloat16(lb);
    }
}

// ---------------------------------------------------------------------------
// Tensor-core fused MLP via mma.sync bf16 (3-term split, fp32 accum).
// ---------------------------------------------------------------------------
#define LDB     272
#define MATSZ   (128 * LDB)
#define AH_OFF  0
#define AL_OFF  MATSZ
#define W1H_OFF (2 * MATSZ)
#define W1L_OFF (3 * MATSZ)
#define W2H_OFF (4 * MATSZ)
#define W2L_OFF (5 * MATSZ)
#define PB1_OFF (6 * MATSZ)
#define PS_OFF  (PB1_OFF + 512)
#define PT_OFF  (PS_OFF + 512)
#define SMEM_REQ (PT_OFF + 512)

__device__ __forceinline__ void gemm3(uint32_t sbase, uint32_t ahOff, uint32_t alOff,
                                      uint32_t whOff, uint32_t wlOff,
                                      int wm, int wn, int lane, float acc[2][8][4]) {
    const int lane15 = lane & 15;
    const int lhalf  = (lane >> 4) << 3;
    const uint32_t aRowBase = (uint32_t)(wm * 32 + lane15) * LDB + (uint32_t)lhalf * 2;
    const uint32_t bBaseOff = (uint32_t)lane15 * LDB + (uint32_t)(wn * 64 + lhalf) * 2;
    #pragma unroll 1
    for (int term = 0; term < 3; term++) {
        uint32_t aOff = (term == 2) ? alOff : ahOff;
        uint32_t wOff = (term == 1) ? wlOff : whOff;
        uint32_t aBase = sbase + aOff + aRowBase;
        uint32_t bBase = sbase + wOff + bBaseOff;
        #pragma unroll
        for (int ks = 0; ks < 8; ks++) {
            uint32_t a0[4], a1[4];
            ldm_x4(a0, aBase + ks * 32);
            ldm_x4(a1, aBase + 16 * LDB + ks * 32);
            uint32_t b[4][4];
            #pragma unroll
            for (int np = 0; np < 4; np++)
                ldm_x4t(b[np], bBase + (uint32_t)ks * (16 * LDB) + np * 32);
            #pragma unroll
            for (int nt = 0; nt < 8; nt++) {
                mma_bf16(acc[0][nt], a0, b[nt >> 1][(nt & 1) * 2], b[nt >> 1][(nt & 1) * 2 + 1]);
                mma_bf16(acc[1][nt], a1, b[nt >> 1][(nt & 1) * 2], b[nt >> 1][(nt & 1) * 2 + 1]);
            }
        }
    }
}

__global__ void __launch_bounds__(256, 1) mlp_mma_k(
    float* __restrict__ out, int layer,
    const float* __restrict__ b1, const float* __restrict__ b2,
    const float* __restrict__ gamma, const float* __restrict__ beta,
    const float* __restrict__ bmean, const float* __restrict__ bvar)
{
    extern __shared__ char sm[];
    const uint32_t sbase = smem_u32(sm);
    const int tid  = threadIdx.x;
    const int wid  = tid >> 5;
    const int lane = tid & 31;
    const int wm   = wid & 3;
    const int wn   = wid >> 2;

    float* B1f = (float*)(sm + PB1_OFF);
    float* Sf  = (float*)(sm + PS_OFF);
    float* Tf  = (float*)(sm + PT_OFF);
    if (tid < 128) {
        float s = __ldg(&gamma[tid]) * rsqrtf(__ldg(&bvar[tid]) + BN_EPS);
        Sf[tid]  = s;
        Tf[tid]  = __ldg(&b2[tid]) * s + __ldg(&beta[tid]) - __ldg(&bmean[tid]) * s;
        B1f[tid] = __ldg(&b1[tid]);
    }

    {
        const uint4* wsrc = (const uint4*)(g_wb + (size_t)layer * 4 * 16384);
        #pragma unroll
        for (int it = 0; it < 32; it++) {
            int idx = tid + it * 256;
            int mat = idx >> 11;
            int j   = idx & 2047;
            int k   = j >> 4, c = j & 15;
            *(uint4*)(sm + W1H_OFF + mat * MATSZ + k * LDB + c * 16) = __ldg(&wsrc[idx]);
        }
    }
    __syncthreads();

    const int rEp = lane >> 2;
    const int cEp = (lane & 3) * 2;

    for (int t = blockIdx.x; t < NTILES; t += gridDim.x) {
        const int rowBase = t * 128;

        #pragma unroll
        for (int i = 0; i < 16; i++) {
            int idx = tid + i * 256;
            int ar = idx >> 5, c4 = idx & 31;
            int gr = rowBase + ar;
            float4 v = make_float4(0.f, 0.f, 0.f, 0.f);
            if (gr < NN) v = __ldg(((const float4*)g_pooled) + (size_t)gr * 32 + c4);
            uint16_t hx,lx,hy,ly,hz,lz,hw,lw;
            split_bf(v.x,hx,lx); split_bf(v.y,hy,ly); split_bf(v.z,hz,lz); split_bf(v.w,hw,lw);
            uint32_t off = (uint32_t)ar * LDB + (uint32_t)c4 * 8;
            uint2 hv = make_uint2((uint32_t)hx | ((uint32_t)hy << 16),
                                  (uint32_t)hz | ((uint32_t)hw << 16));
            uint2 lv = make_uint2((uint32_t)lx | ((uint32_t)ly << 16),
                                  (uint32_t)lz | ((uint32_t)lw << 16));
            *(uint2*)(sm + AH_OFF + off) = hv;
            *(uint2*)(sm + AL_OFF + off) = lv;
        }
        __syncthreads();

        float acc[2][8][4];
        #pragma unroll
        for (int a = 0; a < 2; a++)
            #pragma unroll
            for (int b = 0; b < 8; b++)
                #pragma unroll
                for (int c = 0; c < 4; c++) acc[a][b][c] = 0.f;

        gemm3(sbase, AH_OFF, AL_OFF, W1H_OFF, W1L_OFF, wm, wn, lane, acc);
        __syncthreads();

        #pragma unroll
        for (int mt = 0; mt < 2; mt++) {
            #pragma unroll
            for (int nt = 0; nt < 8; nt++) {
                int row = wm * 32 + mt * 16 + rEp;
                int col = wn * 64 + nt * 8 + cEp;
                float f0 = fmaxf(acc[mt][nt][0] + B1f[col],     0.f);
                float f1 = fmaxf(acc[mt][nt][1] + B1f[col + 1], 0.f);
                float f2 = fmaxf(acc[mt][nt][2] + B1f[col],     0.f);
                float f3 = fmaxf(acc[mt][nt][3] + B1f[col + 1], 0.f);
                uint16_t h0,l0,h1,l1,h2,l2,h3,l3;
                split_bf(f0,h0,l0); split_bf(f1,h1,l1);
                split_bf(f2,h2,l2); split_bf(f3,h3,l3);
                uint32_t o0 = (uint32_t)row * LDB + (uint32_t)col * 2;
                uint32_t o1 = o0 + 8 * LDB;
                *(uint32_t*)(sm + AH_OFF + o0) = (uint32_t)h0 | ((uint32_t)h1 << 16);
                *(uint32_t*)(sm + AL_OFF + o0) = (uint32_t)l0 | ((uint32_t)l1 << 16);
                *(uint32_t*)(sm + AH_OFF + o1) = (uint32_t)h2 | ((uint32_t)h3 << 16);
                *(uint32_t*)(sm + AL_OFF + o1) = (uint32_t)l2 | ((uint32_t)l3 << 16);
            }
        }
        __syncthreads();

        #pragma unroll
        for (int a = 0; a < 2; a++)
            #pragma unroll
            for (int b = 0; b < 8; b++)
                #pragma unroll
                for (int c = 0; c < 4; c++) acc[a][b][c] = 0.f;

        gemm3(sbase, AH_OFF, AL_OFF, W2H_OFF, W2L_OFF, wm, wn, lane, acc);

        #pragma unroll
        for (int mt = 0; mt < 2; mt++) {
            #pragma unroll
            for (int nt = 0; nt < 8; nt++) {
                int row = wm * 32 + mt * 16 + rEp;
                int col = wn * 64 + nt * 8 + cEp;
                int gr0 = rowBase + row;
                int gr1 = gr0 + 8;
                float2 o0, o1;
                o0.x = fmaxf(fmaf(acc[mt][nt][0], Sf[col],     Tf[col]),     0.f);
                o0.y = fmaxf(fmaf(acc[mt][nt][1], Sf[col + 1], Tf[col + 1]), 0.f);
                o1.x = fmaxf(fmaf(acc[mt][nt][2], Sf[col],     Tf[col]),     0.f);
                o1.y = fmaxf(fmaf(acc[mt][nt][3], Sf[col + 1], Tf[col + 1]), 0.f);
                if (gr0 < NN) *(float2*)(out + (size_t)gr0 * D + col) = o0;
                if (gr1 < NN) *(float2*)(out + (size_t)gr1 * D + col) = o1;
            }
        }
        __syncthreads();
    }
}

// ---------------------------------------------------------------------------
extern "C" void kernel_launch(void* const* d_in, const int* in_sizes, int n_in,
                              void* d_out, int out_size) {
    const float* x     = (const float*)d_in[0];
    const int*   esrc  = (const int*)  d_in[1];
    const int*   edst  = (const int*)  d_in[2];
    const float* eps   = (const float*)d_in[3];
    const float* W1    = (const float*)d_in[4];
    const float* b1    = (const float*)d_in[5];
    const float* W2    = (const float*)d_in[6];
    const float* b2    = (const float*)d_in[7];
    const float* gamma = (const float*)d_in[8];
    const float* beta  = (const float*)d_in[9];
    const float* bmean = (const float*)d_in[10];
    const float* bvar  = (const float*)d_in[11];
    float* out = (float*)d_out;

    static int smem_set = 0;
    if (!smem_set) {
        cudaFuncSetAttribute(mlp_mma_k, cudaFuncAttributeMaxDynamicSharedMemorySize, SMEM_REQ);
        smem_set = 1;
    }

    // hidden_rep[0] = x
    cudaMemcpyAsync(out, x, (size_t)NN * D * sizeof(float), cudaMemcpyDeviceToDevice);

    // one-shot: weight split + CSR build
    prep_w_k<<<NL * 2, 256>>>(W1, W2);
    zero_off_k<<<(NN + 256) / 256, 256>>>();
    hist_k<<<(NE + 255) / 256, 256>>>(edst);
    scan_k<<<1, 1024>>>();
    fill_k<<<(NE + 255) / 256, 256>>>(esrc, edst);

    const int aggGrid = (NN * 32 + 255) / 256;   // 6250

    for (int l = 0; l < NL; l++) {
        const float* h  = out + (size_t)l * NN * D;
        float*       hn = out + (size_t)(l + 1) * NN * D;
        agg_k<<<aggGrid, 256>>>(h, eps, l);
        mlp_mma_k<<<148, 256, SMEM_REQ>>>(hn, l,
            b1 + (size_t)l * D, b2 + (size_t)l * D,
            gamma + (size_t)l * D, beta + (size_t)l * D,
            bmean + (size_t)l * D, bvar + (size_t)l * D);
    }
}

// round 6
// speedup vs baseline: 2.3572x; 1.1722x over previous
#include <cuda_runtime.h>
#include <cuda_bf16.h>
#include <cstdint>
#include <cstddef>

#define NN 50000
#define NE 800000
#define D  128
#define NL 5
#define BN_EPS 1e-3f
#define NTILES ((NN + 127) / 128)   // 391

// ---------------- scratch (no allocs allowed) ----------------
__device__ float g_pooled[NN * D];
__device__ __nv_bfloat16 g_wb[NL * 4 * 16384];   // W1h W1l W2h W2l per layer
__device__ int g_off[NN + 1];                    // CSR offsets (by dst)
__device__ int g_cur[NN];                        // counts, then fill cursors
__device__ int g_csr[NE];                        // src ids grouped by dst
#define SCAN_BLK 1024
#define SCAN_NB  ((NN + SCAN_BLK - 1) / SCAN_BLK)   // 49
__device__ int g_bsum[SCAN_NB];

// ---------------- helpers ----------------
__device__ __forceinline__ uint32_t smem_u32(const void* p) {
    uint32_t a;
    asm("{ .reg .u64 t; cvta.to.shared.u64 t, %1; cvt.u32.u64 %0, t; }" : "=r"(a) : "l"(p));
    return a;
}
__device__ __forceinline__ void split_bf(float v, uint16_t& h, uint16_t& l) {
    __nv_bfloat16 hb = __float2bfloat16_rn(v);
    float rem = v - __bfloat162float(hb);
    h = __bfloat16_as_ushort(hb);
    l = __bfloat16_as_ushort(__float2bfloat16_rn(rem));
}
__device__ __forceinline__ void ldm_x4(uint32_t (&r)[4], uint32_t addr) {
    asm volatile("ldmatrix.sync.aligned.m8n8.x4.shared.b16 {%0,%1,%2,%3}, [%4];"
                 : "=r"(r[0]), "=r"(r[1]), "=r"(r[2]), "=r"(r[3]) : "r"(addr));
}
__device__ __forceinline__ void ldm_x4t(uint32_t (&r)[4], uint32_t addr) {
    asm volatile("ldmatrix.sync.aligned.m8n8.x4.trans.shared.b16 {%0,%1,%2,%3}, [%4];"
                 : "=r"(r[0]), "=r"(r[1]), "=r"(r[2]), "=r"(r[3]) : "r"(addr));
}
__device__ __forceinline__ void mma_bf16(float (&d)[4], const uint32_t (&a)[4],
                                         uint32_t b0, uint32_t b1) {
    asm volatile("mma.sync.aligned.m16n8k16.row.col.f32.bf16.bf16.f32 "
                 "{%0,%1,%2,%3}, {%4,%5,%6,%7}, {%8,%9}, {%0,%1,%2,%3};"
                 : "+f"(d[0]), "+f"(d[1]), "+f"(d[2]), "+f"(d[3])
                 : "r"(a[0]), "r"(a[1]), "r"(a[2]), "r"(a[3]), "r"(b0), "r"(b1));
}
#define PBAR(id) asm volatile("bar.sync %0, 64;" :: "r"((id) + 1) : "memory")

// ---------------------------------------------------------------------------
// CSR build (once per launch; edge list is launch-invariant)
// ---------------------------------------------------------------------------
__global__ void zero_off_k() {
    int i = blockIdx.x * 256 + threadIdx.x;
    if (i <= NN) g_off[i] = 0;
}
__global__ void hist_k(const int* __restrict__ dst) {
    int e = blockIdx.x * 256 + threadIdx.x;
    if (e < NE) atomicAdd(&g_off[__ldg(&dst[e]) + 1], 1);
}
// pass A: per-block inclusive scan of counts; block totals -> g_bsum; counts -> g_cur
__global__ void scanA_k() {
    __shared__ int wsum[32];
    const int tid  = threadIdx.x;
    const int lane = tid & 31;
    const int wid  = tid >> 5;
    int i = blockIdx.x * SCAN_BLK + tid;
    int c = (i < NN) ? g_off[i + 1] : 0;
    int v = c;
    #pragma unroll
    for (int d = 1; d < 32; d <<= 1) {
        int t = __shfl_up_sync(0xFFFFFFFFu, v, d);
        if (lane >= d) v += t;
    }
    if (lane == 31) wsum[wid] = v;
    __syncthreads();
    if (wid == 0) {
        int w = wsum[lane];
        #pragma unroll
        for (int d = 1; d < 32; d <<= 1) {
            int t = __shfl_up_sync(0xFFFFFFFFu, w, d);
            if (lane >= d) w += t;
        }
        wsum[lane] = w;
    }
    __syncthreads();
    int inc = v + (wid > 0 ? wsum[wid - 1] : 0);
    if (i < NN) {
        g_off[i + 1] = inc;   // block-local inclusive
        g_cur[i] = c;         // stash count for pass C
    }
    if (tid == SCAN_BLK - 1) g_bsum[blockIdx.x] = inc;
}
// pass B: scan the 49 block totals (1 block, 64 threads)
__global__ void scanB_k() {
    __shared__ int s[64];
    int t = threadIdx.x;
    int v = (t < SCAN_NB) ? g_bsum[t] : 0;
    int lane = t & 31, wid = t >> 5;
    int x = v;
    #pragma unroll
    for (int d = 1; d < 32; d <<= 1) {
        int u = __shfl_up_sync(0xFFFFFFFFu, x, d);
        if (lane >= d) x += u;
    }
    if (lane == 31) s[wid] = x;
    __syncthreads();
    int inc = x + (wid > 0 ? s[0] : 0);
    if (t < SCAN_NB) g_bsum[t] = inc;
}
// pass C: add block prefix; produce final g_off (inclusive) + g_cur (exclusive)
__global__ void scanC_k() {
    int i = blockIdx.x * SCAN_BLK + threadIdx.x;
    if (i >= NN) return;
    int add = (blockIdx.x > 0) ? g_bsum[blockIdx.x - 1] : 0;
    int inc = g_off[i + 1] + add;
    g_off[i + 1] = inc;
    g_cur[i] = inc - g_cur[i];
}
__global__ void fill_k(const int* __restrict__ src, const int* __restrict__ dst) {
    int e = blockIdx.x * 256 + threadIdx.x;
    if (e >= NE) return;
    int p = atomicAdd(&g_cur[__ldg(&dst[e])], 1);
    g_csr[p] = __ldg(&src[e]);
}

// ---------------------------------------------------------------------------
// Aggregation: pooled[d] = (1+eps)*h[d] + sum_{src in csr[off[d]..off[d+1])} h[src]
// ---------------------------------------------------------------------------
__global__ void agg_k(const float* __restrict__ h,
                      const float* __restrict__ eps, int l) {
    int gt   = blockIdx.x * 256 + threadIdx.x;
    int node = gt >> 5;
    int lane = gt & 31;
    if (node >= NN) return;
    float e = 1.0f + __ldg(&eps[l]);
    float4 acc = __ldg(((const float4*)h) + (size_t)node * 32 + lane);
    acc.x *= e; acc.y *= e; acc.z *= e; acc.w *= e;
    int beg = g_off[node], end = g_off[node + 1];
    int j = beg;
    for (; j + 4 <= end; j += 4) {
        int s0 = __ldg(&g_csr[j]);
        int s1 = __ldg(&g_csr[j + 1]);
        int s2 = __ldg(&g_csr[j + 2]);
        int s3 = __ldg(&g_csr[j + 3]);
        float4 v0 = __ldg(((const float4*)h) + (size_t)s0 * 32 + lane);
        float4 v1 = __ldg(((const float4*)h) + (size_t)s1 * 32 + lane);
        float4 v2 = __ldg(((const float4*)h) + (size_t)s2 * 32 + lane);
        float4 v3 = __ldg(((const float4*)h) + (size_t)s3 * 32 + lane);
        acc.x += v0.x + v1.x + v2.x + v3.x;
        acc.y += v0.y + v1.y + v2.y + v3.y;
        acc.z += v0.z + v1.z + v2.z + v3.z;
        acc.w += v0.w + v1.w + v2.w + v3.w;
    }
    for (; j < end; j++) {
        int s0 = __ldg(&g_csr[j]);
        float4 v0 = __ldg(((const float4*)h) + (size_t)s0 * 32 + lane);
        acc.x += v0.x; acc.y += v0.y; acc.z += v0.z; acc.w += v0.w;
    }
    ((float4*)g_pooled)[(size_t)node * 32 + lane] = acc;
}

// ---------------------------------------------------------------------------
// Weight prep: fp32 W[k][n] -> bf16 hi/lo, row-major. grid = NL*2.
// ---------------------------------------------------------------------------
__global__ void prep_w_k(const float* __restrict__ W1, const float* __restrict__ W2) {
    int l   = blockIdx.x >> 1;
    int mat = blockIdx.x & 1;
    const float* W = (mat ? W2 : W1) + (size_t)l * 16384;
    __nv_bfloat16* dh = g_wb + ((size_t)(l * 2 + mat) * 2 + 0) * 16384;
    __nv_bfloat16* dl = g_wb + ((size_t)(l * 2 + mat) * 2 + 1) * 16384;
    for (int i = threadIdx.x; i < 16384; i += 256) {
        uint16_t hb, lb;
        split_bf(__ldg(&W[i]), hb, lb);
        dh[i] = __ushort_as_bfloat16(hb);
        dl[i] = __ushort_as_bfloat16(lb);
    }
}

// ---------------------------------------------------------------------------
// Tensor-core fused MLP via mma.sync bf16 (3-term split, fp32 accum).
// 4 independent warp-pair pipelines per CTA (named barriers, no block sync
// inside the tile loop) — pairs drift out of phase so MMA overlaps epilogues.
// ---------------------------------------------------------------------------
#define LDB     272
#define MATSZ   (128 * LDB)
#define AH_OFF  0
#define AL_OFF  MATSZ
#define W1H_OFF (2 * MATSZ)
#define W1L_OFF (3 * MATSZ)
#define W2H_OFF (4 * MATSZ)
#define W2L_OFF (5 * MATSZ)
#define PB1_OFF (6 * MATSZ)
#define PS_OFF  (PB1_OFF + 512)
#define PT_OFF  (PS_OFF + 512)
#define SMEM_REQ (PT_OFF + 512)

__device__ __forceinline__ void gemm3(uint32_t sbase, uint32_t ahOff, uint32_t alOff,
                                      uint32_t whOff, uint32_t wlOff,
                                      int wm, int wn, int lane, float acc[2][8][4]) {
    const int lane15 = lane & 15;
    const int lhalf  = (lane >> 4) << 3;
    const uint32_t aRowBase = (uint32_t)(wm * 32 + lane15) * LDB + (uint32_t)lhalf * 2;
    const uint32_t bBaseOff = (uint32_t)lane15 * LDB + (uint32_t)(wn * 64 + lhalf) * 2;
    #pragma unroll 1
    for (int term = 0; term < 3; term++) {
        uint32_t aOff = (term == 2) ? alOff : ahOff;
        uint32_t wOff = (term == 1) ? wlOff : whOff;
        uint32_t aBase = sbase + aOff + aRowBase;
        uint32_t bBase = sbase + wOff + bBaseOff;
        #pragma unroll
        for (int ks = 0; ks < 8; ks++) {
            uint32_t a0[4], a1[4];
            ldm_x4(a0, aBase + ks * 32);
            ldm_x4(a1, aBase + 16 * LDB + ks * 32);
            uint32_t b[4][4];
            #pragma unroll
            for (int np = 0; np < 4; np++)
                ldm_x4t(b[np], bBase + (uint32_t)ks * (16 * LDB) + np * 32);
            #pragma unroll
            for (int nt = 0; nt < 8; nt++) {
                mma_bf16(acc[0][nt], a0, b[nt >> 1][(nt & 1) * 2], b[nt >> 1][(nt & 1) * 2 + 1]);
                mma_bf16(acc[1][nt], a1, b[nt >> 1][(nt & 1) * 2], b[nt >> 1][(nt & 1) * 2 + 1]);
            }
        }
    }
}

__global__ void __launch_bounds__(256, 1) mlp_mma_k(
    float* __restrict__ out, int layer,
    const float* __restrict__ b1, const float* __restrict__ b2,
    const float* __restrict__ gamma, const float* __restrict__ beta,
    const float* __restrict__ bmean, const float* __restrict__ bvar)
{
    extern __shared__ char sm[];
    const uint32_t sbase = smem_u32(sm);
    const int tid  = threadIdx.x;
    const int wid  = tid >> 5;
    const int lane = tid & 31;
    const int wm   = wid & 3;
    const int wn   = wid >> 2;
    const int ptid = (wn << 5) | lane;    // 0..63 within the pair

    float* B1f = (float*)(sm + PB1_OFF);
    float* Sf  = (float*)(sm + PS_OFF);
    float* Tf  = (float*)(sm + PT_OFF);
    if (tid < 128) {
        float s = __ldg(&gamma[tid]) * rsqrtf(__ldg(&bvar[tid]) + BN_EPS);
        Sf[tid]  = s;
        Tf[tid]  = __ldg(&b2[tid]) * s + __ldg(&beta[tid]) - __ldg(&bmean[tid]) * s;
        B1f[tid] = __ldg(&b1[tid]);
    }

    {
        const uint4* wsrc = (const uint4*)(g_wb + (size_t)layer * 4 * 16384);
        #pragma unroll
        for (int it = 0; it < 32; it++) {
            int idx = tid + it * 256;
            int mat = idx >> 11;
            int j   = idx & 2047;
            int k   = j >> 4, c = j & 15;
            *(uint4*)(sm + W1H_OFF + mat * MATSZ + k * LDB + c * 16) = __ldg(&wsrc[idx]);
        }
    }
    __syncthreads();

    const int rEp = lane >> 2;
    const int cEp = (lane & 3) * 2;

    for (int t = blockIdx.x; t < NTILES; t += gridDim.x) {
        const int rowBase = t * 128;

        // ---- pair loads + splits its own 32 rows ----
        #pragma unroll
        for (int i = 0; i < 16; i++) {
            int idx = ptid + i * 64;               // 0..1023
            int ar = wm * 32 + (idx >> 5), c4 = idx & 31;
            int gr = rowBase + ar;
            float4 v = make_float4(0.f, 0.f, 0.f, 0.f);
            if (gr < NN) v = __ldg(((const float4*)g_pooled) + (size_t)gr * 32 + c4);
            uint16_t hx,lx,hy,ly,hz,lz,hw,lw;
            split_bf(v.x,hx,lx); split_bf(v.y,hy,ly); split_bf(v.z,hz,lz); split_bf(v.w,hw,lw);
            uint32_t off = (uint32_t)ar * LDB + (uint32_t)c4 * 8;
            uint2 hv = make_uint2((uint32_t)hx | ((uint32_t)hy << 16),
                                  (uint32_t)hz | ((uint32_t)hw << 16));
            uint2 lv = make_uint2((uint32_t)lx | ((uint32_t)ly << 16),
                                  (uint32_t)lz | ((uint32_t)lw << 16));
            *(uint2*)(sm + AH_OFF + off) = hv;
            *(uint2*)(sm + AL_OFF + off) = lv;
        }
        PBAR(wm);

        float acc[2][8][4];
        #pragma unroll
        for (int a = 0; a < 2; a++)
            #pragma unroll
            for (int b = 0; b < 8; b++)
                #pragma unroll
                for (int c = 0; c < 4; c++) acc[a][b][c] = 0.f;

        gemm3(sbase, AH_OFF, AL_OFF, W1H_OFF, W1L_OFF, wm, wn, lane, acc);
        PBAR(wm);   // both warps of pair done reading A rows

        // ---- epilogue 1: Z = relu(D1 + b1) -> split back into AH/AL ----
        #pragma unroll
        for (int mt = 0; mt < 2; mt++) {
            #pragma unroll
            for (int nt = 0; nt < 8; nt++) {
                int row = wm * 32 + mt * 16 + rEp;
                int col = wn * 64 + nt * 8 + cEp;
                float f0 = fmaxf(acc[mt][nt][0] + B1f[col],     0.f);
                float f1 = fmaxf(acc[mt][nt][1] + B1f[col + 1], 0.f);
                float f2 = fmaxf(acc[mt][nt][2] + B1f[col],     0.f);
                float f3 = fmaxf(acc[mt][nt][3] + B1f[col + 1], 0.f);
                uint16_t h0,l0,h1,l1,h2,l2,h3,l3;
                split_bf(f0,h0,l0); split_bf(f1,h1,l1);
                split_bf(f2,h2,l2); split_bf(f3,h3,l3);
                uint32_t o0 = (uint32_t)row * LDB + (uint32_t)col * 2;
                uint32_t o1 = o0 + 8 * LDB;
                *(uint32_t*)(sm + AH_OFF + o0) = (uint32_t)h0 | ((uint32_t)h1 << 16);
                *(uint32_t*)(sm + AL_OFF + o0) = (uint32_t)l0 | ((uint32_t)l1 << 16);
                *(uint32_t*)(sm + AH_OFF + o1) = (uint32_t)h2 | ((uint32_t)h3 << 16);
                *(uint32_t*)(sm + AL_OFF + o1) = (uint32_t)l2 | ((uint32_t)l3 << 16);
            }
        }
        PBAR(wm);

        #pragma unroll
        for (int a = 0; a < 2; a++)
            #pragma unroll
            for (int b = 0; b < 8; b++)
                #pragma unroll
                for (int c = 0; c < 4; c++) acc[a][b][c] = 0.f;

        gemm3(sbase, AH_OFF, AL_OFF, W2H_OFF, W2L_OFF, wm, wn, lane, acc);
        PBAR(wm);   // both warps of pair done reading Z before next-tile A write

        // ---- epilogue 2: out = relu(D2 * S + T) ----
        #pragma unroll
        for (int mt = 0; mt < 2; mt++) {
            #pragma unroll
            for (int nt = 0; nt < 8; nt++) {
                int row = wm * 32 + mt * 16 + rEp;
                int col = wn * 64 + nt * 8 + cEp;
                int gr0 = rowBase + row;
                int gr1 = gr0 + 8;
                float2 o0, o1;
                o0.x = fmaxf(fmaf(acc[mt][nt][0], Sf[col],     Tf[col]),     0.f);
                o0.y = fmaxf(fmaf(acc[mt][nt][1], Sf[col + 1], Tf[col + 1]), 0.f);
                o1.x = fmaxf(fmaf(acc[mt][nt][2], Sf[col],     Tf[col]),     0.f);
                o1.y = fmaxf(fmaf(acc[mt][nt][3], Sf[col + 1], Tf[col + 1]), 0.f);
                if (gr0 < NN) *(float2*)(out + (size_t)gr0 * D + col) = o0;
                if (gr1 < NN) *(float2*)(out + (size_t)gr1 * D + col) = o1;
            }
        }
    }
}

// ---------------------------------------------------------------------------
extern "C" void kernel_launch(void* const* d_in, const int* in_sizes, int n_in,
                              void* d_out, int out_size) {
    const float* x     = (const float*)d_in[0];
    const int*   esrc  = (const int*)  d_in[1];
    const int*   edst  = (const int*)  d_in[2];
    const float* eps   = (const float*)d_in[3];
    const float* W1    = (const float*)d_in[4];
    const float* b1    = (const float*)d_in[5];
    const float* W2    = (const float*)d_in[6];
    const float* b2    = (const float*)d_in[7];
    const float* gamma = (const float*)d_in[8];
    const float* beta  = (const float*)d_in[9];
    const float* bmean = (const float*)d_in[10];
    const float* bvar  = (const float*)d_in[11];
    float* out = (float*)d_out;

    static int smem_set = 0;
    if (!smem_set) {
        cudaFuncSetAttribute(mlp_mma_k, cudaFuncAttributeMaxDynamicSharedMemorySize, SMEM_REQ);
        smem_set = 1;
    }

    // hidden_rep[0] = x
    cudaMemcpyAsync(out, x, (size_t)NN * D * sizeof(float), cudaMemcpyDeviceToDevice);

    // one-shot: weight split + CSR build
    prep_w_k<<<NL * 2, 256>>>(W1, W2);
    zero_off_k<<<(NN + 256) / 256, 256>>>();
    hist_k<<<(NE + 255) / 256, 256>>>(edst);
    scanA_k<<<SCAN_NB, SCAN_BLK>>>();
    scanB_k<<<1, 64>>>();
    scanC_k<<<SCAN_NB, SCAN_BLK>>>();
    fill_k<<<(NE + 255) / 256, 256>>>(esrc, edst);

    const int aggGrid = (NN * 32 + 255) / 256;   // 6250

    for (int l = 0; l < NL; l++) {
        const float* h  = out + (size_t)l * NN * D;
        float*       hn = out + (size_t)(l + 1) * NN * D;
        agg_k<<<aggGrid, 256>>>(h, eps, l);
        mlp_mma_k<<<148, 256, SMEM_REQ>>>(hn, l,
            b1 + (size_t)l * D, b2 + (size_t)l * D,
            gamma + (size_t)l * D, beta + (size_t)l * D,
            bmean + (size_t)l * D, bvar + (size_t)l * D);
    }
}